// round 11
// baseline (speedup 1.0000x reference)
#include <cuda_runtime.h>

#define NLEV 16
#define LOG2_T 19
#define TSIZE (1u << LOG2_T)
#define TMASK (TSIZE - 1u)
#define PRIME_Y 2654435761u
#define PRIME_Z 805459861u

#define CAP   2200000
#define NBINS (1 << 18)      // 18-bit Morton key at res 64
#define BPT   (NBINS / 1024) // bins per thread in the single-block scan

typedef unsigned long long ull;

// Static scratch (allocation-free): sorted coords, permutation, histogram.
__device__ float4   g_xs[CAP];
__device__ int      g_perm[CAP];
__device__ unsigned g_hist[NBINS];

// ---------------- sorting pre-pass ----------------

__device__ __forceinline__ unsigned morton_key(float x0, float x1, float x2) {
    int cx = (int)(x0 * 64.0f); cx = cx < 0 ? 0 : (cx > 63 ? 63 : cx);
    int cy = (int)(x1 * 64.0f); cy = cy < 0 ? 0 : (cy > 63 ? 63 : cy);
    int cz = (int)(x2 * 64.0f); cz = cz < 0 ? 0 : (cz > 63 ? 63 : cz);
    unsigned m = 0;
    #pragma unroll
    for (int d = 0; d < 6; d++) {
        m |= ((unsigned)(cx >> d) & 1u) << (3 * d + 0);
        m |= ((unsigned)(cy >> d) & 1u) << (3 * d + 1);
        m |= ((unsigned)(cz >> d) & 1u) << (3 * d + 2);
    }
    return m;
}

__global__ void zero_hist_k() {
    int i = blockIdx.x * blockDim.x + threadIdx.x;
    if (i < NBINS) g_hist[i] = 0u;
}

__global__ void hist_k(const float* __restrict__ x, int N) {
    int i = blockIdx.x * blockDim.x + threadIdx.x;
    if (i >= N) return;
    float x0 = x[3 * i + 0] * 0.5f + 0.5f;
    float x1 = x[3 * i + 1] * 0.5f + 0.5f;
    float x2 = x[3 * i + 2] * 0.5f + 0.5f;
    atomicAdd(&g_hist[morton_key(x0, x1, x2)], 1u);
}

// Single-block exclusive scan of g_hist: 1024 threads x BPT bins each,
// two sequential passes over own chunk (read-sum, then rewrite prefix).
__global__ void scan_k() {
    __shared__ unsigned sm[1024];
    const int t = threadIdx.x;
    const int base = t * BPT;
    unsigned s = 0;
    for (int k = 0; k < BPT; k++) s += g_hist[base + k];
    sm[t] = s;
    __syncthreads();
    for (int off = 1; off < 1024; off <<= 1) {
        unsigned v = (t >= off) ? sm[t - off] : 0u;
        __syncthreads();
        sm[t] += v;
        __syncthreads();
    }
    unsigned run = sm[t] - s;            // exclusive prefix of this chunk
    for (int k = 0; k < BPT; k++) {
        unsigned v = g_hist[base + k];
        g_hist[base + k] = run;
        run += v;
    }
}

__global__ void scatter_k(const float* __restrict__ x, int N) {
    int i = blockIdx.x * blockDim.x + threadIdx.x;
    if (i >= N) return;
    float x0 = x[3 * i + 0] * 0.5f + 0.5f;
    float x1 = x[3 * i + 1] * 0.5f + 0.5f;
    float x2 = x[3 * i + 2] * 0.5f + 0.5f;
    unsigned key = morton_key(x0, x1, x2);
    unsigned slot = atomicAdd(&g_hist[key], 1u);
    g_xs[slot] = make_float4(x0, x1, x2, 0.0f);
    g_perm[slot] = i;
}

// ---------------- main fused kernel (exact R5 best) ----------------

// packed fp32x2 FMA (full-precision fp32, 2 lanes per instruction)
__device__ __forceinline__ ull fma2u(ull a, ull b, ull c) {
    ull d;
    asm("fma.rn.f32x2 %0, %1, %2, %3;" : "=l"(d) : "l"(a), "l"(b), "l"(c));
    return d;
}
__device__ __forceinline__ ull pack2(float lo, float hi) {
    ull r;
    asm("mov.b64 %0, {%1, %2};" : "=l"(r) : "f"(lo), "f"(hi));
    return r;
}
__device__ __forceinline__ void unpack2(ull v, float& lo, float& hi) {
    asm("mov.b64 {%0, %1}, %2;" : "=f"(lo), "=f"(hi) : "l"(v));
}

__global__ __launch_bounds__(256, 2)
void hashgrid_mlp_kernel(const float2* __restrict__ tables,
                         const float*  __restrict__ resolutions,
                         const float*  __restrict__ W1, const float* __restrict__ b1,
                         const float*  __restrict__ W2, const float* __restrict__ b2,
                         const float*  __restrict__ W3, const float* __restrict__ b3,
                         float* __restrict__ out, int N)
{
    __shared__ __align__(16) float sW1[32 * 64];
    __shared__ __align__(16) float sW2[64 * 64];
    __shared__ __align__(16) float sB1[64];
    __shared__ __align__(16) float sB2[64];
    __shared__ __align__(16) float sW3[64];
    __shared__ __align__(16) float sRes[16];
    __shared__ float sB3;

    const int tid = threadIdx.x;
    for (int k = tid; k < 32 * 64; k += blockDim.x) sW1[k] = W1[k];
    for (int k = tid; k < 64 * 64; k += blockDim.x) sW2[k] = W2[k];
    if (tid < 64) { sB1[tid] = b1[tid]; sB2[tid] = b2[tid]; sW3[tid] = W3[tid]; }
    if (tid < 16) sRes[tid] = resolutions[tid];
    if (tid == 0) sB3 = b3[0];
    __syncthreads();

    const int i = blockIdx.x * blockDim.x + tid;
    if (i >= N) return;

    const float4 xs = g_xs[i];           // sorted, already mapped to [0,1]
    const float x0 = xs.x, x1 = xs.y, x2 = xs.z;

    // h1 accumulators: 32 packed f32x2 = neurons (2j, 2j+1); init with bias
    ull h1u[32];
    #pragma unroll
    for (int j = 0; j < 32; j++) h1u[j] = ((const ull*)sB1)[j];

    // two-stage pipeline for the per-level gathers.
    float2   tbuf[2][8];
    float    wbuf[2][3];
    unsigned mbuf[2];

    auto issue = [&](int L, float2* tb, float* wb, unsigned& mb) {
        const float res = sRes[L];
        const float px = x0 * res, py = x1 * res, pz = x2 * res;
        const float fx = floorf(px), fy = floorf(py), fz = floorf(pz);
        wb[0] = px - fx; wb[1] = py - fy; wb[2] = pz - fz;
        const unsigned cx = (unsigned)fx, cy = (unsigned)fy, cz = (unsigned)fz;
        const unsigned hy0 = cy * PRIME_Y, hy1 = hy0 + PRIME_Y;
        const unsigned hz0 = cz * PRIME_Z, hz1 = hz0 + PRIME_Z;
        unsigned rr[4];
        rr[0] = hy0 ^ hz0; rr[1] = hy1 ^ hz0; rr[2] = hy0 ^ hz1; rr[3] = hy1 ^ hz1;
        const float2* __restrict__ base = tables + (size_t)L * TSIZE;
        unsigned m = 0;
        if (!(cx & 1u)) {
            // cx even: idx(cx+1) = idx(cx) ^ 1 -> one aligned float4 per (y,z) combo
            #pragma unroll
            for (int j = 0; j < 4; j++) {
                const unsigned i0 = (cx ^ rr[j]) & TMASK;
                m |= (i0 & 1u) << j;            // slot order swapped iff idx(cx) is odd
                const float4 v = __ldg((const float4*)(base + (i0 & ~1u)));
                tb[2 * j]     = make_float2(v.x, v.y);
                tb[2 * j + 1] = make_float2(v.z, v.w);
            }
        } else {
            #pragma unroll
            for (int j = 0; j < 4; j++) {
                const unsigned i0 = (cx        ^ rr[j]) & TMASK;
                const unsigned i1 = ((cx + 1u) ^ rr[j]) & TMASK;
                tb[2 * j]     = __ldg(base + i0);
                tb[2 * j + 1] = __ldg(base + i1);
            }
        }
        mb = m;
    };

    issue(0, tbuf[0], wbuf[0], mbuf[0]);

    #pragma unroll
    for (int L = 0; L < NLEV; L++) {
        const int cur = L & 1;
        if (L < NLEV - 1) issue(L + 1, tbuf[cur ^ 1], wbuf[cur ^ 1], mbuf[cur ^ 1]);

        // trilinear interpolation for level L (consumes prefetched tbuf[cur])
        const float wx1 = wbuf[cur][0], wy1 = wbuf[cur][1], wz1 = wbuf[cur][2];
        const float wx0 = 1.0f - wx1, wy0 = 1.0f - wy1, wz0 = 1.0f - wz1;
        float wyz[4];
        wyz[0] = wy0 * wz0; wyz[1] = wy1 * wz0; wyz[2] = wy0 * wz1; wyz[3] = wy1 * wz1;
        const float2* t = tbuf[cur];
        const unsigned m = mbuf[cur];
        float f0 = 0.0f, f1 = 0.0f;
        #pragma unroll
        for (int j = 0; j < 4; j++) {
            const bool  s  = (m >> j) & 1u;
            const float wl = s ? wx1 : wx0;      // weight for slot 2j
            const float wh = s ? wx0 : wx1;      // weight for slot 2j+1
            const float cl = wl * wyz[j], ch = wh * wyz[j];
            f0 += cl * t[2 * j].x + ch * t[2 * j + 1].x;
            f1 += cl * t[2 * j].y + ch * t[2 * j + 1].y;
        }

        // stream the 2 features of this level straight into layer-1 accumulators
        const ull a0 = pack2(f0, f0);
        const ull a1 = pack2(f1, f1);
        const ulonglong2* __restrict__ wv =
            (const ulonglong2*)(sW1 + (2 * L) * 64);   // row 2L then row 2L+1
        #pragma unroll
        for (int q = 0; q < 16; q++) {
            ulonglong2 Wp = wv[q];                     // LDS.128, broadcast
            h1u[2 * q]     = fma2u(a0, Wp.x, h1u[2 * q]);
            h1u[2 * q + 1] = fma2u(a0, Wp.y, h1u[2 * q + 1]);
        }
        #pragma unroll
        for (int q = 0; q < 16; q++) {
            ulonglong2 Wp = wv[16 + q];
            h1u[2 * q]     = fma2u(a1, Wp.x, h1u[2 * q]);
            h1u[2 * q + 1] = fma2u(a1, Wp.y, h1u[2 * q + 1]);
        }
    }

    // ---- layer 2 (relu(h1) @ W2 + b2) and layer 3 fused, 2 tiles of 32 neurons ----
    float outv = sB3;
    #pragma unroll
    for (int tile = 0; tile < 2; tile++) {
        ull acc[16];
        #pragma unroll
        for (int m = 0; m < 16; m++)
            acc[m] = ((const ull*)(sB2 + tile * 32))[m];

        #pragma unroll
        for (int k = 0; k < 64; k++) {
            float lo, hi;
            unpack2(h1u[k >> 1], lo, hi);
            float v = (k & 1) ? hi : lo;
            v = fmaxf(v, 0.0f);                        // relu on layer-1 activation
            const ull r = pack2(v, v);
            const ulonglong2* __restrict__ wrow =
                (const ulonglong2*)(sW2 + k * 64 + tile * 32);
            #pragma unroll
            for (int m = 0; m < 8; m++) {
                ulonglong2 Wp = wrow[m];               // LDS.128, broadcast
                acc[2 * m]     = fma2u(r, Wp.x, acc[2 * m]);
                acc[2 * m + 1] = fma2u(r, Wp.y, acc[2 * m + 1]);
            }
        }
        #pragma unroll
        for (int m = 0; m < 16; m++) {
            float e0, e1;
            unpack2(acc[m], e0, e1);
            outv += fmaxf(e0, 0.0f) * sW3[tile * 32 + 2 * m]
                  + fmaxf(e1, 0.0f) * sW3[tile * 32 + 2 * m + 1];
        }
    }

    out[g_perm[i]] = outv;               // route back to original order
}

extern "C" void kernel_launch(void* const* d_in, const int* in_sizes, int n_in,
                              void* d_out, int out_size)
{
    const float*  x    = (const float*) d_in[0];
    const float2* tabs = (const float2*)d_in[1];
    const float*  res  = (const float*) d_in[2];
    const float*  W1   = (const float*) d_in[3];
    const float*  b1   = (const float*) d_in[4];
    const float*  W2   = (const float*) d_in[5];
    const float*  b2   = (const float*) d_in[6];
    const float*  W3   = (const float*) d_in[7];
    const float*  b3   = (const float*) d_in[8];

    const int N = in_sizes[0] / 3;
    const int threads = 256;
    const int blocks = (N + threads - 1) / threads;

    // spatial binning presort (all graph-capturable kernel launches)
    zero_hist_k<<<(NBINS + 255) / 256, 256>>>();
    hist_k<<<blocks, threads>>>(x, N);
    scan_k<<<1, 1024>>>();
    scatter_k<<<blocks, threads>>>(x, N);

    hashgrid_mlp_kernel<<<blocks, threads>>>(tabs, res, W1, b1, W2, b2, W3, b3,
                                             (float*)d_out, N);
}

// round 12
// speedup vs baseline: 1.4103x; 1.4103x over previous
#include <cuda_runtime.h>

#define NLEV 16
#define LOG2_T 19
#define TSIZE (1u << LOG2_T)
#define TMASK (TSIZE - 1u)
#define PRIME_Y 2654435761u
#define PRIME_Z 805459861u

#define CAP   2200000
#define NBINS (1 << 18)      // 18-bit Morton key at res 64
#define NCHUNK 256           // NBINS / 1024

typedef unsigned long long ull;

// Static scratch (allocation-free): sorted coords, permutation, histogram.
__device__ float4   g_xs[CAP];
__device__ int      g_perm[CAP];
__device__ unsigned g_hist[NBINS];
__device__ unsigned g_bsum[NCHUNK];

// ---------------- sorting pre-pass ----------------

__device__ __forceinline__ unsigned morton_key(float x0, float x1, float x2) {
    int cx = (int)(x0 * 64.0f); cx = cx < 0 ? 0 : (cx > 63 ? 63 : cx);
    int cy = (int)(x1 * 64.0f); cy = cy < 0 ? 0 : (cy > 63 ? 63 : cy);
    int cz = (int)(x2 * 64.0f); cz = cz < 0 ? 0 : (cz > 63 ? 63 : cz);
    unsigned m = 0;
    #pragma unroll
    for (int d = 0; d < 6; d++) {
        m |= ((unsigned)(cx >> d) & 1u) << (3 * d + 0);
        m |= ((unsigned)(cy >> d) & 1u) << (3 * d + 1);
        m |= ((unsigned)(cz >> d) & 1u) << (3 * d + 2);
    }
    return m;
}

__global__ void zero_hist_k() {
    int i = blockIdx.x * blockDim.x + threadIdx.x;
    if (i < NBINS) g_hist[i] = 0u;
}

__global__ void hist_k(const float* __restrict__ x, int N) {
    int i = blockIdx.x * blockDim.x + threadIdx.x;
    if (i >= N) return;
    float x0 = x[3 * i + 0] * 0.5f + 0.5f;
    float x1 = x[3 * i + 1] * 0.5f + 0.5f;
    float x2 = x[3 * i + 2] * 0.5f + 0.5f;
    atomicAdd(&g_hist[morton_key(x0, x1, x2)], 1u);
}

// Hierarchical scan: (1) per-chunk exclusive scan (256 CTAs x 1024 bins),
// (2) scan of chunk totals, (3) add chunk offsets.
__global__ void scan1_k() {
    __shared__ unsigned sm[1024];
    const int t = threadIdx.x;
    const int g = blockIdx.x * 1024 + t;
    const unsigned v = g_hist[g];
    sm[t] = v;
    __syncthreads();
    for (int off = 1; off < 1024; off <<= 1) {
        unsigned u = (t >= off) ? sm[t - off] : 0u;
        __syncthreads();
        sm[t] += u;
        __syncthreads();
    }
    g_hist[g] = sm[t] - v;               // exclusive within chunk
    if (t == 1023) g_bsum[blockIdx.x] = sm[t];
}

__global__ void scan2_k() {
    __shared__ unsigned sm[NCHUNK];
    const int t = threadIdx.x;
    const unsigned v = g_bsum[t];
    sm[t] = v;
    __syncthreads();
    for (int off = 1; off < NCHUNK; off <<= 1) {
        unsigned u = (t >= off) ? sm[t - off] : 0u;
        __syncthreads();
        sm[t] += u;
        __syncthreads();
    }
    g_bsum[t] = sm[t] - v;               // exclusive chunk offsets
}

__global__ void add_k() {
    const int g = blockIdx.x * 1024 + threadIdx.x;
    g_hist[g] += g_bsum[blockIdx.x];
}

__global__ void scatter_k(const float* __restrict__ x, int N) {
    int i = blockIdx.x * blockDim.x + threadIdx.x;
    if (i >= N) return;
    float x0 = x[3 * i + 0] * 0.5f + 0.5f;
    float x1 = x[3 * i + 1] * 0.5f + 0.5f;
    float x2 = x[3 * i + 2] * 0.5f + 0.5f;
    unsigned key = morton_key(x0, x1, x2);
    unsigned slot = atomicAdd(&g_hist[key], 1u);
    g_xs[slot] = make_float4(x0, x1, x2, 0.0f);
    g_perm[slot] = i;
}

// ---------------- main fused kernel (exact R5 best) ----------------

// packed fp32x2 FMA (full-precision fp32, 2 lanes per instruction)
__device__ __forceinline__ ull fma2u(ull a, ull b, ull c) {
    ull d;
    asm("fma.rn.f32x2 %0, %1, %2, %3;" : "=l"(d) : "l"(a), "l"(b), "l"(c));
    return d;
}
__device__ __forceinline__ ull pack2(float lo, float hi) {
    ull r;
    asm("mov.b64 %0, {%1, %2};" : "=l"(r) : "f"(lo), "f"(hi));
    return r;
}
__device__ __forceinline__ void unpack2(ull v, float& lo, float& hi) {
    asm("mov.b64 {%0, %1}, %2;" : "=f"(lo), "=f"(hi) : "l"(v));
}

__global__ __launch_bounds__(256, 2)
void hashgrid_mlp_kernel(const float2* __restrict__ tables,
                         const float*  __restrict__ resolutions,
                         const float*  __restrict__ W1, const float* __restrict__ b1,
                         const float*  __restrict__ W2, const float* __restrict__ b2,
                         const float*  __restrict__ W3, const float* __restrict__ b3,
                         float* __restrict__ out, int N)
{
    __shared__ __align__(16) float sW1[32 * 64];
    __shared__ __align__(16) float sW2[64 * 64];
    __shared__ __align__(16) float sB1[64];
    __shared__ __align__(16) float sB2[64];
    __shared__ __align__(16) float sW3[64];
    __shared__ __align__(16) float sRes[16];
    __shared__ float sB3;

    const int tid = threadIdx.x;
    for (int k = tid; k < 32 * 64; k += blockDim.x) sW1[k] = W1[k];
    for (int k = tid; k < 64 * 64; k += blockDim.x) sW2[k] = W2[k];
    if (tid < 64) { sB1[tid] = b1[tid]; sB2[tid] = b2[tid]; sW3[tid] = W3[tid]; }
    if (tid < 16) sRes[tid] = resolutions[tid];
    if (tid == 0) sB3 = b3[0];
    __syncthreads();

    const int i = blockIdx.x * blockDim.x + tid;
    if (i >= N) return;

    const float4 xs = g_xs[i];           // sorted, already mapped to [0,1]
    const float x0 = xs.x, x1 = xs.y, x2 = xs.z;

    // h1 accumulators: 32 packed f32x2 = neurons (2j, 2j+1); init with bias
    ull h1u[32];
    #pragma unroll
    for (int j = 0; j < 32; j++) h1u[j] = ((const ull*)sB1)[j];

    // two-stage pipeline for the per-level gathers.
    float2   tbuf[2][8];
    float    wbuf[2][3];
    unsigned mbuf[2];

    auto issue = [&](int L, float2* tb, float* wb, unsigned& mb) {
        const float res = sRes[L];
        const float px = x0 * res, py = x1 * res, pz = x2 * res;
        const float fx = floorf(px), fy = floorf(py), fz = floorf(pz);
        wb[0] = px - fx; wb[1] = py - fy; wb[2] = pz - fz;
        const unsigned cx = (unsigned)fx, cy = (unsigned)fy, cz = (unsigned)fz;
        const unsigned hy0 = cy * PRIME_Y, hy1 = hy0 + PRIME_Y;
        const unsigned hz0 = cz * PRIME_Z, hz1 = hz0 + PRIME_Z;
        unsigned rr[4];
        rr[0] = hy0 ^ hz0; rr[1] = hy1 ^ hz0; rr[2] = hy0 ^ hz1; rr[3] = hy1 ^ hz1;
        const float2* __restrict__ base = tables + (size_t)L * TSIZE;
        unsigned m = 0;
        if (!(cx & 1u)) {
            // cx even: idx(cx+1) = idx(cx) ^ 1 -> one aligned float4 per (y,z) combo
            #pragma unroll
            for (int j = 0; j < 4; j++) {
                const unsigned i0 = (cx ^ rr[j]) & TMASK;
                m |= (i0 & 1u) << j;            // slot order swapped iff idx(cx) is odd
                const float4 v = __ldg((const float4*)(base + (i0 & ~1u)));
                tb[2 * j]     = make_float2(v.x, v.y);
                tb[2 * j + 1] = make_float2(v.z, v.w);
            }
        } else {
            #pragma unroll
            for (int j = 0; j < 4; j++) {
                const unsigned i0 = (cx        ^ rr[j]) & TMASK;
                const unsigned i1 = ((cx + 1u) ^ rr[j]) & TMASK;
                tb[2 * j]     = __ldg(base + i0);
                tb[2 * j + 1] = __ldg(base + i1);
            }
        }
        mb = m;
    };

    issue(0, tbuf[0], wbuf[0], mbuf[0]);

    #pragma unroll
    for (int L = 0; L < NLEV; L++) {
        const int cur = L & 1;
        if (L < NLEV - 1) issue(L + 1, tbuf[cur ^ 1], wbuf[cur ^ 1], mbuf[cur ^ 1]);

        // trilinear interpolation for level L (consumes prefetched tbuf[cur])
        const float wx1 = wbuf[cur][0], wy1 = wbuf[cur][1], wz1 = wbuf[cur][2];
        const float wx0 = 1.0f - wx1, wy0 = 1.0f - wy1, wz0 = 1.0f - wz1;
        float wyz[4];
        wyz[0] = wy0 * wz0; wyz[1] = wy1 * wz0; wyz[2] = wy0 * wz1; wyz[3] = wy1 * wz1;
        const float2* t = tbuf[cur];
        const unsigned m = mbuf[cur];
        float f0 = 0.0f, f1 = 0.0f;
        #pragma unroll
        for (int j = 0; j < 4; j++) {
            const bool  s  = (m >> j) & 1u;
            const float wl = s ? wx1 : wx0;      // weight for slot 2j
            const float wh = s ? wx0 : wx1;      // weight for slot 2j+1
            const float cl = wl * wyz[j], ch = wh * wyz[j];
            f0 += cl * t[2 * j].x + ch * t[2 * j + 1].x;
            f1 += cl * t[2 * j].y + ch * t[2 * j + 1].y;
        }

        // stream the 2 features of this level straight into layer-1 accumulators
        const ull a0 = pack2(f0, f0);
        const ull a1 = pack2(f1, f1);
        const ulonglong2* __restrict__ wv =
            (const ulonglong2*)(sW1 + (2 * L) * 64);   // row 2L then row 2L+1
        #pragma unroll
        for (int q = 0; q < 16; q++) {
            ulonglong2 Wp = wv[q];                     // LDS.128, broadcast
            h1u[2 * q]     = fma2u(a0, Wp.x, h1u[2 * q]);
            h1u[2 * q + 1] = fma2u(a0, Wp.y, h1u[2 * q + 1]);
        }
        #pragma unroll
        for (int q = 0; q < 16; q++) {
            ulonglong2 Wp = wv[16 + q];
            h1u[2 * q]     = fma2u(a1, Wp.x, h1u[2 * q]);
            h1u[2 * q + 1] = fma2u(a1, Wp.y, h1u[2 * q + 1]);
        }
    }

    // ---- layer 2 (relu(h1) @ W2 + b2) and layer 3 fused, 2 tiles of 32 neurons ----
    float outv = sB3;
    #pragma unroll
    for (int tile = 0; tile < 2; tile++) {
        ull acc[16];
        #pragma unroll
        for (int m = 0; m < 16; m++)
            acc[m] = ((const ull*)(sB2 + tile * 32))[m];

        #pragma unroll
        for (int k = 0; k < 64; k++) {
            float lo, hi;
            unpack2(h1u[k >> 1], lo, hi);
            float v = (k & 1) ? hi : lo;
            v = fmaxf(v, 0.0f);                        // relu on layer-1 activation
            const ull r = pack2(v, v);
            const ulonglong2* __restrict__ wrow =
                (const ulonglong2*)(sW2 + k * 64 + tile * 32);
            #pragma unroll
            for (int m = 0; m < 8; m++) {
                ulonglong2 Wp = wrow[m];               // LDS.128, broadcast
                acc[2 * m]     = fma2u(r, Wp.x, acc[2 * m]);
                acc[2 * m + 1] = fma2u(r, Wp.y, acc[2 * m + 1]);
            }
        }
        #pragma unroll
        for (int m = 0; m < 16; m++) {
            float e0, e1;
            unpack2(acc[m], e0, e1);
            outv += fmaxf(e0, 0.0f) * sW3[tile * 32 + 2 * m]
                  + fmaxf(e1, 0.0f) * sW3[tile * 32 + 2 * m + 1];
        }
    }

    out[g_perm[i]] = outv;               // route back to original order
}

extern "C" void kernel_launch(void* const* d_in, const int* in_sizes, int n_in,
                              void* d_out, int out_size)
{
    const float*  x    = (const float*) d_in[0];
    const float2* tabs = (const float2*)d_in[1];
    const float*  res  = (const float*) d_in[2];
    const float*  W1   = (const float*) d_in[3];
    const float*  b1   = (const float*) d_in[4];
    const float*  W2   = (const float*) d_in[5];
    const float*  b2   = (const float*) d_in[6];
    const float*  W3   = (const float*) d_in[7];
    const float*  b3   = (const float*) d_in[8];

    const int N = in_sizes[0] / 3;
    const int threads = 256;
    const int blocks = (N + threads - 1) / threads;

    // spatial binning presort (all graph-capturable kernel launches)
    zero_hist_k<<<(NBINS + 255) / 256, 256>>>();
    hist_k<<<blocks, threads>>>(x, N);
    scan1_k<<<NCHUNK, 1024>>>();
    scan2_k<<<1, NCHUNK>>>();
    add_k<<<NCHUNK, 1024>>>();
    scatter_k<<<blocks, threads>>>(x, N);

    hashgrid_mlp_kernel<<<blocks, threads>>>(tabs, res, W1, b1, W2, b2, W3, b3,
                                             (float*)d_out, N);
}